// round 4
// baseline (speedup 1.0000x reference)
#include <cuda_runtime.h>
#include <cuda_bf16.h>

// Fused GraphSAGE layer, warp-specialized pipeline:
//   agg[n]  = (sum_s features[neigh[n,s]] + features[node[n]]) / (S+1)
//   out[n]  = l2norm(relu(agg[n] @ W + b))
//
// 512 threads/block, 2 blocks/SM. Threads [256,512) = GATHER group (producer):
// gathers tile i+1 into smem buffer (i+1)&1. Threads [0,256) = GEMM group
// (consumer): 8 rows x 4 cols register tile on buffer i&1, bias/relu,
// shuffle-based row L2-norm, direct normalized store. Double-buffered smem,
// one __syncthreads per pipeline step. DRAM-bound gather overlaps
// FFMA-bound GEMM structurally.

#define BM      32
#define DDIM    256
#define THREADS 512
#define MAX_S   40

// dynamic smem layout:
//   As[2][BM][DDIM] floats            (64 KB)
//   idxS[2][BM*MAX_S] ints            (10 KB)
//   normS[BM*2] floats                (256 B)
#define AS_BYTES   (2 * BM * DDIM * 4)
#define IDX_BYTES  (2 * BM * MAX_S * 4)
#define SMEM_BYTES (AS_BYTES + IDX_BYTES + BM * 2 * 4)

__global__ __launch_bounds__(THREADS, 2)
void gsage_pipe_kernel(const int*   __restrict__ node_idx,
                       const int*   __restrict__ neigh_idx,
                       const float* __restrict__ features,
                       const float* __restrict__ W,
                       const float* __restrict__ b,
                       float*       __restrict__ out,
                       int n_nodes, int n_samp, int ntiles, int gridN)
{
    extern __shared__ char smem[];
    float (*As)[BM][DDIM] = reinterpret_cast<float(*)[BM][DDIM]>(smem);
    int*   idxS  = reinterpret_cast<int*>(smem + AS_BYTES);          // [2][BM*MAX_S]
    float* normS = reinterpret_cast<float*>(smem + AS_BYTES + IDX_BYTES); // [BM*2]

    const int tid  = threadIdx.x;
    const int S    = n_samp + 1;
    const bool is_gather = (tid >= 256);
    const int  g_tid     = tid & 255;

    // per-block tile list: bid, bid+gridN, ...
    const int bid = blockIdx.x;
    const int J   = (ntiles - bid + gridN - 1) / gridN;   // tiles for this block
    if (J <= 0) return;  // uniform per block; no barrier hazard

    // ---- GEMM-role constants (harmless for gather group) ----
    const int ct      = g_tid & 63;        // cols 4*ct .. 4*ct+3
    const int rt      = g_tid >> 6;        // 0..3
    const int rowBase = rt * 8;            // 8 rows per thread
    const int lane    = g_tid & 31;
    const int half    = (g_tid >> 5) & 1;  // which warp of the rt pair
    const float4 bias = __ldg(&reinterpret_cast<const float4*>(b)[ct]);
    const float4* W4  = reinterpret_cast<const float4*>(W);
    const float4* F4  = reinterpret_cast<const float4*>(features);
    float4* out4      = reinterpret_cast<float4*>(out);

    const float invS = 1.0f / (float)S;

    for (int i = 0; i <= J; ++i) {
        __syncthreads();   // buffer handoff: gather(i-1) complete, gemm(i-2) complete

        if (is_gather) {
            // ================= PRODUCER: gather tile i into buffer i&1 ========
            if (i < J) {
                const int tile      = bid + i * gridN;
                const int blockBase = tile * BM;
                const int rows      = min(BM, n_nodes - blockBase);
                const int buf       = i & 1;
                int* idxT = idxS + buf * (BM * MAX_S);

                // stage indices: [n*S + s], slot 0 = self
                for (int e = g_tid; e < rows * S; e += 256) {
                    int n = e / S, s = e - n * S;
                    int gn = blockBase + n;
                    idxT[n * S + s] = (s == 0) ? node_idx[gn]
                                               : neigh_idx[(long)gn * n_samp + (s - 1)];
                }
                asm volatile("bar.sync 1, 256;" ::: "memory");

                // c4 column of float4, 8 nodes per thread in two passes of 4
                const int c4  = g_tid & 63;
                const int grp = g_tid >> 6;   // 0..3
                #pragma unroll
                for (int h = 0; h < 2; ++h) {
                    const int n0 = grp * 8 + h * 4;
                    const bool v0 = (n0 + 0) < rows;
                    const bool v1 = (n0 + 1) < rows;
                    const bool v2 = (n0 + 2) < rows;
                    const bool v3 = (n0 + 3) < rows;
                    const int* ip0 = idxT + (v0 ? (n0 + 0) * S : 0);
                    const int* ip1 = idxT + (v1 ? (n0 + 1) * S : 0);
                    const int* ip2 = idxT + (v2 ? (n0 + 2) * S : 0);
                    const int* ip3 = idxT + (v3 ? (n0 + 3) * S : 0);

                    float4 a0 = {0,0,0,0}, a1 = {0,0,0,0}, a2 = {0,0,0,0}, a3 = {0,0,0,0};
                    #pragma unroll 2
                    for (int s = 0; s < S; ++s) {
                        float4 t0 = __ldg(F4 + (long)ip0[s] * (DDIM/4) + c4);
                        float4 t1 = __ldg(F4 + (long)ip1[s] * (DDIM/4) + c4);
                        float4 t2 = __ldg(F4 + (long)ip2[s] * (DDIM/4) + c4);
                        float4 t3 = __ldg(F4 + (long)ip3[s] * (DDIM/4) + c4);
                        a0.x += t0.x; a0.y += t0.y; a0.z += t0.z; a0.w += t0.w;
                        a1.x += t1.x; a1.y += t1.y; a1.z += t1.z; a1.w += t1.w;
                        a2.x += t2.x; a2.y += t2.y; a2.z += t2.z; a2.w += t2.w;
                        a3.x += t3.x; a3.y += t3.y; a3.z += t3.z; a3.w += t3.w;
                    }
                    const float m0 = v0 ? invS : 0.0f, m1 = v1 ? invS : 0.0f;
                    const float m2 = v2 ? invS : 0.0f, m3 = v3 ? invS : 0.0f;
                    a0.x *= m0; a0.y *= m0; a0.z *= m0; a0.w *= m0;
                    a1.x *= m1; a1.y *= m1; a1.z *= m1; a1.w *= m1;
                    a2.x *= m2; a2.y *= m2; a2.z *= m2; a2.w *= m2;
                    a3.x *= m3; a3.y *= m3; a3.z *= m3; a3.w *= m3;

                    reinterpret_cast<float4*>(&As[buf][n0 + 0][0])[c4] = a0;
                    reinterpret_cast<float4*>(&As[buf][n0 + 1][0])[c4] = a1;
                    reinterpret_cast<float4*>(&As[buf][n0 + 2][0])[c4] = a2;
                    reinterpret_cast<float4*>(&As[buf][n0 + 3][0])[c4] = a3;
                }
            }
        } else {
            // ================= CONSUMER: GEMM + epilogue on tile i-1 ==========
            if (i >= 1) {
                const int tile      = bid + (i - 1) * gridN;
                const int blockBase = tile * BM;
                const int rows      = min(BM, n_nodes - blockBase);
                const int buf       = (i - 1) & 1;
                const float (*A)[DDIM] = As[buf];

                float acc[8][4];
                #pragma unroll
                for (int r = 0; r < 8; ++r)
                    #pragma unroll
                    for (int c = 0; c < 4; ++c) acc[r][c] = 0.0f;

                #pragma unroll 4
                for (int k = 0; k < DDIM; ++k) {
                    float4 w = __ldg(&W4[k * (DDIM/4) + ct]);
                    float a[8];
                    #pragma unroll
                    for (int r = 0; r < 8; ++r) a[r] = A[rowBase + r][k]; // broadcast
                    #pragma unroll
                    for (int r = 0; r < 8; ++r) {
                        acc[r][0] = fmaf(a[r], w.x, acc[r][0]);
                        acc[r][1] = fmaf(a[r], w.y, acc[r][1]);
                        acc[r][2] = fmaf(a[r], w.z, acc[r][2]);
                        acc[r][3] = fmaf(a[r], w.w, acc[r][3]);
                    }
                }

                // bias + relu in registers; per-row squared partials
                float sq[8];
                #pragma unroll
                for (int r = 0; r < 8; ++r) {
                    acc[r][0] = fmaxf(acc[r][0] + bias.x, 0.0f);
                    acc[r][1] = fmaxf(acc[r][1] + bias.y, 0.0f);
                    acc[r][2] = fmaxf(acc[r][2] + bias.z, 0.0f);
                    acc[r][3] = fmaxf(acc[r][3] + bias.w, 0.0f);
                    float s = acc[r][0] * acc[r][0];
                    s = fmaf(acc[r][1], acc[r][1], s);
                    s = fmaf(acc[r][2], acc[r][2], s);
                    s = fmaf(acc[r][3], acc[r][3], s);
                    sq[r] = s;
                }
                // warp reduce each row partial (lanes share the same rows)
                #pragma unroll
                for (int r = 0; r < 8; ++r) {
                    #pragma unroll
                    for (int o = 16; o > 0; o >>= 1)
                        sq[r] += __shfl_xor_sync(0xffffffffu, sq[r], o);
                }
                if (lane == 0) {
                    #pragma unroll
                    for (int r = 0; r < 8; ++r)
                        normS[(rowBase + r) * 2 + half] = sq[r];
                }
                asm volatile("bar.sync 2, 256;" ::: "memory");

                // normalize + store
                #pragma unroll
                for (int r = 0; r < 8; ++r) {
                    int row = rowBase + r;
                    if (row < rows) {
                        float nsum = normS[row * 2] + normS[row * 2 + 1];
                        float inv  = 1.0f / fmaxf(sqrtf(nsum), 1e-12f);
                        float4 v;
                        v.x = acc[r][0] * inv;
                        v.y = acc[r][1] * inv;
                        v.z = acc[r][2] * inv;
                        v.w = acc[r][3] * inv;
                        out4[(long)(blockBase + row) * (DDIM/4) + ct] = v;
                    }
                }
            }
        }
    }
}

extern "C" void kernel_launch(void* const* d_in, const int* in_sizes, int n_in,
                              void* d_out, int out_size)
{
    const int*   node_idx  = (const int*)  d_in[0];
    const int*   neigh_idx = (const int*)  d_in[1];
    const float* features  = (const float*)d_in[2];
    const float* W         = (const float*)d_in[3];
    const float* b         = (const float*)d_in[4];
    float*       out       = (float*)      d_out;

    const int n_nodes = in_sizes[0];
    const int n_samp  = in_sizes[1] / n_nodes;   // 32
    const int ntiles  = (n_nodes + BM - 1) / BM;
    const int gridN   = (ntiles < 296) ? ntiles : 296;   // 2 blocks x 148 SMs

    cudaFuncSetAttribute(gsage_pipe_kernel,
                         cudaFuncAttributeMaxDynamicSharedMemorySize, SMEM_BYTES);

    gsage_pipe_kernel<<<gridN, THREADS, SMEM_BYTES>>>(node_idx, neigh_idx,
                                                      features, W, b, out,
                                                      n_nodes, n_samp,
                                                      ntiles, gridN);
}

// round 5
// speedup vs baseline: 1.6480x; 1.6480x over previous
#include <cuda_runtime.h>
#include <cuda_bf16.h>
#include <cstdint>

// Fused GraphSAGE layer:
//   agg[n]  = (sum_s features[neigh[n,s]] + features[node[n]]) / (S+1)
//   out[n]  = l2norm(relu(agg[n] @ W + b))
//
// One block = 32 nodes, 512 threads, 2 blocks/SM.
// Phase 1: float4 gather (R2-proven), agg stored as tf32 bits in smem
//          (row stride 260 -> conflict-free mma fragment loads).
// Phase 2: tf32 mma.sync m16n8k8 tensor-core GEMM. 16 warps:
//          warp w -> m-half (w&1)*16, n-stripe (w>>1)*32 (4 n8 tiles).
// Phase 3: bias/relu into smem, shuffle row L2-norm, vectorized store.

#define BM      32
#define DDIM    256
#define THREADS 512
#define MAX_S   40
#define ASTRIDE 260                 // floats per smem row (pad for banks)

#define AS_FLOATS (BM * ASTRIDE)
#define AS_BYTES  (AS_FLOATS * 4)
#define IDX_BYTES (BM * MAX_S * 4)
#define SMEM_BYTES (AS_BYTES + IDX_BYTES + 128)

__device__ __forceinline__ uint32_t f2tf32(float f) {
    uint32_t u;
    asm("cvt.rna.tf32.f32 %0, %1;" : "=r"(u) : "f"(f));
    return u;
}

__device__ __forceinline__ void mma_tf32(float* d,
                                         uint32_t a0, uint32_t a1,
                                         uint32_t a2, uint32_t a3,
                                         uint32_t b0, uint32_t b1)
{
    asm("mma.sync.aligned.m16n8k8.row.col.f32.tf32.tf32.f32 "
        "{%0,%1,%2,%3}, {%4,%5,%6,%7}, {%8,%9}, {%0,%1,%2,%3};"
        : "+f"(d[0]), "+f"(d[1]), "+f"(d[2]), "+f"(d[3])
        : "r"(a0), "r"(a1), "r"(a2), "r"(a3), "r"(b0), "r"(b1));
}

__global__ __launch_bounds__(THREADS, 2)
void gsage_tc_kernel(const int*   __restrict__ node_idx,
                     const int*   __restrict__ neigh_idx,
                     const float* __restrict__ features,
                     const float* __restrict__ W,
                     const float* __restrict__ b,
                     float*       __restrict__ out,
                     int n_nodes, int n_samp)
{
    extern __shared__ char smem[];
    float* As   = reinterpret_cast<float*>(smem);                 // [32][260]
    int*   idxS = reinterpret_cast<int*>(smem + AS_BYTES);        // [32*MAX_S]

    const int tid       = threadIdx.x;
    const int blockBase = blockIdx.x * BM;
    const int rows      = min(BM, n_nodes - blockBase);
    const int S         = n_samp + 1;

    // ---- stage indices: slot 0 = self, slots 1..n_samp = neighbors ----
    for (int i = tid; i < rows * S; i += THREADS) {
        int n = i / S, s = i - n * S;
        int gn = blockBase + n;
        idxS[n * S + s] = (s == 0) ? node_idx[gn]
                                   : neigh_idx[(long)gn * n_samp + (s - 1)];
    }
    __syncthreads();

    // ---- gather + mean: float4 columns, 4 nodes per thread; tf32 store ----
    {
        const int c4  = tid & 63;
        const int n0  = (tid >> 6) * 4;
        const float4* F4 = reinterpret_cast<const float4*>(features);

        const bool v0 = (n0 + 0) < rows;
        const bool v1 = (n0 + 1) < rows;
        const bool v2 = (n0 + 2) < rows;
        const bool v3 = (n0 + 3) < rows;
        const int* ip0 = idxS + (v0 ? (n0 + 0) * S : 0);
        const int* ip1 = idxS + (v1 ? (n0 + 1) * S : 0);
        const int* ip2 = idxS + (v2 ? (n0 + 2) * S : 0);
        const int* ip3 = idxS + (v3 ? (n0 + 3) * S : 0);

        float4 a0 = {0,0,0,0}, a1 = {0,0,0,0}, a2 = {0,0,0,0}, a3 = {0,0,0,0};

        #pragma unroll 2
        for (int s = 0; s < S; ++s) {
            float4 t0 = __ldg(F4 + (long)ip0[s] * (DDIM/4) + c4);
            float4 t1 = __ldg(F4 + (long)ip1[s] * (DDIM/4) + c4);
            float4 t2 = __ldg(F4 + (long)ip2[s] * (DDIM/4) + c4);
            float4 t3 = __ldg(F4 + (long)ip3[s] * (DDIM/4) + c4);
            a0.x += t0.x; a0.y += t0.y; a0.z += t0.z; a0.w += t0.w;
            a1.x += t1.x; a1.y += t1.y; a1.z += t1.z; a1.w += t1.w;
            a2.x += t2.x; a2.y += t2.y; a2.z += t2.z; a2.w += t2.w;
            a3.x += t3.x; a3.y += t3.y; a3.z += t3.z; a3.w += t3.w;
        }

        const float invS = 1.0f / (float)S;
        const float m0 = v0 ? invS : 0.0f, m1 = v1 ? invS : 0.0f;
        const float m2 = v2 ? invS : 0.0f, m3 = v3 ? invS : 0.0f;

        uint4 u0 = { f2tf32(a0.x*m0), f2tf32(a0.y*m0), f2tf32(a0.z*m0), f2tf32(a0.w*m0) };
        uint4 u1 = { f2tf32(a1.x*m1), f2tf32(a1.y*m1), f2tf32(a1.z*m1), f2tf32(a1.w*m1) };
        uint4 u2 = { f2tf32(a2.x*m2), f2tf32(a2.y*m2), f2tf32(a2.z*m2), f2tf32(a2.w*m2) };
        uint4 u3 = { f2tf32(a3.x*m3), f2tf32(a3.y*m3), f2tf32(a3.z*m3), f2tf32(a3.w*m3) };

        *reinterpret_cast<uint4*>(&As[(n0 + 0) * ASTRIDE + 4 * c4]) = u0;
        *reinterpret_cast<uint4*>(&As[(n0 + 1) * ASTRIDE + 4 * c4]) = u1;
        *reinterpret_cast<uint4*>(&As[(n0 + 2) * ASTRIDE + 4 * c4]) = u2;
        *reinterpret_cast<uint4*>(&As[(n0 + 3) * ASTRIDE + 4 * c4]) = u3;
    }
    __syncthreads();

    // ---- tensor-core GEMM: tf32 m16n8k8 ----
    const int lane = tid & 31, warp = tid >> 5;
    const int g    = lane >> 2, t = lane & 3;
    const int mrow = (warp & 1) * 16;         // row half
    const int nbase = (warp >> 1) * 32;       // 32-col stripe, 4 n8 tiles

    float d[4][4];
    #pragma unroll
    for (int j = 0; j < 4; ++j)
        #pragma unroll
        for (int c = 0; c < 4; ++c) d[j][c] = 0.0f;

    const uint32_t* a_lo = reinterpret_cast<const uint32_t*>(As) + (mrow + g) * ASTRIDE;
    const uint32_t* a_hi = a_lo + 8 * ASTRIDE;

    #pragma unroll 2
    for (int k0 = 0; k0 < DDIM; k0 += 8) {
        uint32_t a0 = a_lo[k0 + t];
        uint32_t a1 = a_hi[k0 + t];
        uint32_t a2 = a_lo[k0 + t + 4];
        uint32_t a3 = a_hi[k0 + t + 4];

        #pragma unroll
        for (int j = 0; j < 4; ++j) {
            int n = nbase + 8 * j + g;
            uint32_t b0 = f2tf32(__ldg(&W[(k0 + t)     * DDIM + n]));
            uint32_t b1 = f2tf32(__ldg(&W[(k0 + t + 4) * DDIM + n]));
            mma_tf32(d[j], a0, a1, a2, a3, b0, b1);
        }
    }

    // ---- epilogue: bias + relu into smem (overwrite As after sync) ----
    __syncthreads();
    #pragma unroll
    for (int j = 0; j < 4; ++j) {
        int col = nbase + 8 * j + 2 * t;
        float2 bb = __ldg(reinterpret_cast<const float2*>(b + col));
        float2 lo, hi;
        lo.x = fmaxf(d[j][0] + bb.x, 0.0f);
        lo.y = fmaxf(d[j][1] + bb.y, 0.0f);
        hi.x = fmaxf(d[j][2] + bb.x, 0.0f);
        hi.y = fmaxf(d[j][3] + bb.y, 0.0f);
        *reinterpret_cast<float2*>(&As[(mrow + g)     * ASTRIDE + col]) = lo;
        *reinterpret_cast<float2*>(&As[(mrow + g + 8) * ASTRIDE + col]) = hi;
    }
    __syncthreads();

    // ---- per-row L2 norm: warp w handles rows 2w, 2w+1 ----
    float* invN = reinterpret_cast<float*>(smem + AS_BYTES + IDX_BYTES);
    #pragma unroll
    for (int rr = 0; rr < 2; ++rr) {
        int row = warp * 2 + rr;
        float s = 0.0f;
        #pragma unroll
        for (int jj = 0; jj < 8; ++jj) {
            float v = As[row * ASTRIDE + lane + 32 * jj];
            s = fmaf(v, v, s);
        }
        #pragma unroll
        for (int o = 16; o > 0; o >>= 1)
            s += __shfl_xor_sync(0xffffffffu, s, o);
        if (lane == 0)
            invN[row] = 1.0f / fmaxf(sqrtf(s), 1e-12f);
    }
    __syncthreads();

    // ---- normalized vectorized store ----
    float4* out4 = reinterpret_cast<float4*>(out);
    for (int i = tid; i < BM * (DDIM / 4); i += THREADS) {
        int r = i >> 6, c = i & 63;
        if (r < rows) {
            float4 v = *reinterpret_cast<const float4*>(&As[r * ASTRIDE + 4 * c]);
            float sc = invN[r];
            v.x *= sc; v.y *= sc; v.z *= sc; v.w *= sc;
            out4[(long)(blockBase + r) * (DDIM / 4) + c] = v;
        }
    }
}

extern "C" void kernel_launch(void* const* d_in, const int* in_sizes, int n_in,
                              void* d_out, int out_size)
{
    const int*   node_idx  = (const int*)  d_in[0];
    const int*   neigh_idx = (const int*)  d_in[1];
    const float* features  = (const float*)d_in[2];
    const float* W         = (const float*)d_in[3];
    const float* b         = (const float*)d_in[4];
    float*       out       = (float*)      d_out;

    const int n_nodes = in_sizes[0];
    const int n_samp  = in_sizes[1] / n_nodes;   // 32

    cudaFuncSetAttribute(gsage_tc_kernel,
                         cudaFuncAttributeMaxDynamicSharedMemorySize, SMEM_BYTES);

    const int grid = (n_nodes + BM - 1) / BM;
    gsage_tc_kernel<<<grid, THREADS, SMEM_BYTES>>>(node_idx, neigh_idx,
                                                   features, W, b, out,
                                                   n_nodes, n_samp);
}

// round 6
// speedup vs baseline: 1.8248x; 1.1073x over previous
#include <cuda_runtime.h>
#include <cuda_bf16.h>
#include <cstdint>

// Fused GraphSAGE layer:
//   agg[n]  = (sum_s features[neigh[n,s]] + features[node[n]]) / (S+1)
//   out[n]  = l2norm(relu(agg[n] @ W + b))
//
// One block = 32 nodes, 512 threads, 2 blocks/SM.
// Phase 1: float4 gather (unroll 4 -> 16 LDG.128 in flight), agg stored as
//          tf32 bits in smem (row stride 260 -> conflict-free frag loads).
// Phase 2: tf32 mma.sync m16n8k8. W staged through double-buffered smem
//          chunks (converted to tf32 once, stride 264 -> conflict-free LDS).
// Phase 3: bias/relu into smem, shuffle row L2-norm, vectorized store.

#define BM      32
#define DDIM    256
#define THREADS 512
#define MAX_S   40
#define ASTRIDE 260     // A tile row stride (words)
#define WSTRIDE 264     // W chunk row stride (words)

#define AS_BYTES  (BM * ASTRIDE * 4)                  // 33280
#define WS_BYTES  (2 * 8 * WSTRIDE * 4)               // 16896
#define IDX_BYTES (BM * MAX_S * 4)                    // 5120 (aliases Ws region)
#define R2_BYTES  (WS_BYTES > IDX_BYTES ? WS_BYTES : IDX_BYTES)
#define SMEM_BYTES (AS_BYTES + R2_BYTES + 128)

__device__ __forceinline__ uint32_t f2tf32(float f) {
    uint32_t u;
    asm("cvt.rna.tf32.f32 %0, %1;" : "=r"(u) : "f"(f));
    return u;
}

__device__ __forceinline__ void mma_tf32(float* d,
                                         uint32_t a0, uint32_t a1,
                                         uint32_t a2, uint32_t a3,
                                         uint32_t b0, uint32_t b1)
{
    asm("mma.sync.aligned.m16n8k8.row.col.f32.tf32.tf32.f32 "
        "{%0,%1,%2,%3}, {%4,%5,%6,%7}, {%8,%9}, {%0,%1,%2,%3};"
        : "+f"(d[0]), "+f"(d[1]), "+f"(d[2]), "+f"(d[3])
        : "r"(a0), "r"(a1), "r"(a2), "r"(a3), "r"(b0), "r"(b1));
}

__global__ __launch_bounds__(THREADS, 2)
void gsage_tc_kernel(const int*   __restrict__ node_idx,
                     const int*   __restrict__ neigh_idx,
                     const float* __restrict__ features,
                     const float* __restrict__ W,
                     const float* __restrict__ b,
                     float*       __restrict__ out,
                     int n_nodes, int n_samp)
{
    extern __shared__ char smem[];
    float*    As   = reinterpret_cast<float*>(smem);               // [32][260]
    int*      idxS = reinterpret_cast<int*>(smem + AS_BYTES);      // gather only
    uint32_t* Ws   = reinterpret_cast<uint32_t*>(smem + AS_BYTES); // gemm only
    float*    invN = reinterpret_cast<float*>(smem + AS_BYTES + R2_BYTES);

    const int tid       = threadIdx.x;
    const int blockBase = blockIdx.x * BM;
    const int rows      = min(BM, n_nodes - blockBase);
    const int S         = n_samp + 1;

    // ---- stage indices: slot 0 = self, slots 1..n_samp = neighbors ----
    for (int i = tid; i < rows * S; i += THREADS) {
        int n = i / S, s = i - n * S;
        int gn = blockBase + n;
        idxS[n * S + s] = (s == 0) ? node_idx[gn]
                                   : neigh_idx[(long)gn * n_samp + (s - 1)];
    }
    __syncthreads();

    // ---- gather + mean: float4 columns, 4 nodes per thread; tf32 store ----
    {
        const int c4 = tid & 63;
        const int n0 = (tid >> 6) * 4;
        const float4* F4 = reinterpret_cast<const float4*>(features);

        const bool v0 = (n0 + 0) < rows;
        const bool v1 = (n0 + 1) < rows;
        const bool v2 = (n0 + 2) < rows;
        const bool v3 = (n0 + 3) < rows;
        const int* ip0 = idxS + (v0 ? (n0 + 0) * S : 0);
        const int* ip1 = idxS + (v1 ? (n0 + 1) * S : 0);
        const int* ip2 = idxS + (v2 ? (n0 + 2) * S : 0);
        const int* ip3 = idxS + (v3 ? (n0 + 3) * S : 0);

        float4 a0 = {0,0,0,0}, a1 = {0,0,0,0}, a2 = {0,0,0,0}, a3 = {0,0,0,0};

        #pragma unroll 4
        for (int s = 0; s < S; ++s) {
            float4 t0 = __ldg(F4 + (long)ip0[s] * (DDIM/4) + c4);
            float4 t1 = __ldg(F4 + (long)ip1[s] * (DDIM/4) + c4);
            float4 t2 = __ldg(F4 + (long)ip2[s] * (DDIM/4) + c4);
            float4 t3 = __ldg(F4 + (long)ip3[s] * (DDIM/4) + c4);
            a0.x += t0.x; a0.y += t0.y; a0.z += t0.z; a0.w += t0.w;
            a1.x += t1.x; a1.y += t1.y; a1.z += t1.z; a1.w += t1.w;
            a2.x += t2.x; a2.y += t2.y; a2.z += t2.z; a2.w += t2.w;
            a3.x += t3.x; a3.y += t3.y; a3.z += t3.z; a3.w += t3.w;
        }

        const float invS = 1.0f / (float)S;
        const float m0 = v0 ? invS : 0.0f, m1 = v1 ? invS : 0.0f;
        const float m2 = v2 ? invS : 0.0f, m3 = v3 ? invS : 0.0f;

        uint4 u0 = { f2tf32(a0.x*m0), f2tf32(a0.y*m0), f2tf32(a0.z*m0), f2tf32(a0.w*m0) };
        uint4 u1 = { f2tf32(a1.x*m1), f2tf32(a1.y*m1), f2tf32(a1.z*m1), f2tf32(a1.w*m1) };
        uint4 u2 = { f2tf32(a2.x*m2), f2tf32(a2.y*m2), f2tf32(a2.z*m2), f2tf32(a2.w*m2) };
        uint4 u3 = { f2tf32(a3.x*m3), f2tf32(a3.y*m3), f2tf32(a3.z*m3), f2tf32(a3.w*m3) };

        *reinterpret_cast<uint4*>(&As[(n0 + 0) * ASTRIDE + 4 * c4]) = u0;
        *reinterpret_cast<uint4*>(&As[(n0 + 1) * ASTRIDE + 4 * c4]) = u1;
        *reinterpret_cast<uint4*>(&As[(n0 + 2) * ASTRIDE + 4 * c4]) = u2;
        *reinterpret_cast<uint4*>(&As[(n0 + 3) * ASTRIDE + 4 * c4]) = u3;
    }
    __syncthreads();   // As ready; idxS dead -> Ws region live

    // ---- tensor-core GEMM: tf32 m16n8k8, W staged via smem ----
    const int lane = tid & 31, warp = tid >> 5;
    const int g    = lane >> 2, t = lane & 3;
    const int mrow  = (warp & 1) * 16;
    const int nbase = (warp >> 1) * 32;

    // staging coords: thread -> (kk row 0..7, 4 cols)
    const int kk = tid >> 6;
    const int n4 = (tid & 63) * 4;

    float d[4][4];
    #pragma unroll
    for (int j = 0; j < 4; ++j)
        #pragma unroll
        for (int c = 0; c < 4; ++c) d[j][c] = 0.0f;

    const uint32_t* a_lo = reinterpret_cast<const uint32_t*>(As) + (mrow + g) * ASTRIDE;
    const uint32_t* a_hi = a_lo + 8 * ASTRIDE;

    // prologue: stage chunk 0 into buffer 0
    {
        float4 w = *reinterpret_cast<const float4*>(&W[kk * DDIM + n4]);
        uint4 u = { f2tf32(w.x), f2tf32(w.y), f2tf32(w.z), f2tf32(w.w) };
        *reinterpret_cast<uint4*>(&Ws[kk * WSTRIDE + n4]) = u;
    }
    __syncthreads();

    for (int kc = 0; kc < DDIM / 8; ++kc) {
        const uint32_t* Wb = Ws + (kc & 1) * (8 * WSTRIDE);

        // stage next chunk into other buffer
        if (kc + 1 < DDIM / 8) {
            float4 w = *reinterpret_cast<const float4*>(
                           &W[((kc + 1) * 8 + kk) * DDIM + n4]);
            uint4 u = { f2tf32(w.x), f2tf32(w.y), f2tf32(w.z), f2tf32(w.w) };
            *reinterpret_cast<uint4*>(
                &Ws[((kc + 1) & 1) * (8 * WSTRIDE) + kk * WSTRIDE + n4]) = u;
        }

        const int k0 = kc * 8;
        uint32_t fa0 = a_lo[k0 + t];
        uint32_t fa1 = a_hi[k0 + t];
        uint32_t fa2 = a_lo[k0 + t + 4];
        uint32_t fa3 = a_hi[k0 + t + 4];

        #pragma unroll
        for (int j = 0; j < 4; ++j) {
            int n = nbase + 8 * j + g;
            uint32_t b0 = Wb[t * WSTRIDE + n];            // conflict-free
            uint32_t b1 = Wb[(t + 4) * WSTRIDE + n];
            mma_tf32(d[j], fa0, fa1, fa2, fa3, b0, b1);
        }
        __syncthreads();
    }

    // ---- epilogue: bias + relu into smem (overwrite As) ----
    #pragma unroll
    for (int j = 0; j < 4; ++j) {
        int col = nbase + 8 * j + 2 * t;
        float2 bb = __ldg(reinterpret_cast<const float2*>(b + col));
        float2 lo, hi;
        lo.x = fmaxf(d[j][0] + bb.x, 0.0f);
        lo.y = fmaxf(d[j][1] + bb.y, 0.0f);
        hi.x = fmaxf(d[j][2] + bb.x, 0.0f);
        hi.y = fmaxf(d[j][3] + bb.y, 0.0f);
        *reinterpret_cast<float2*>(&As[(mrow + g)     * ASTRIDE + col]) = lo;
        *reinterpret_cast<float2*>(&As[(mrow + g + 8) * ASTRIDE + col]) = hi;
    }
    __syncthreads();

    // ---- per-row L2 norm: warp w handles rows 2w, 2w+1 ----
    #pragma unroll
    for (int rr = 0; rr < 2; ++rr) {
        int row = warp * 2 + rr;
        float s = 0.0f;
        #pragma unroll
        for (int jj = 0; jj < 8; ++jj) {
            float v = As[row * ASTRIDE + lane + 32 * jj];
            s = fmaf(v, v, s);
        }
        #pragma unroll
        for (int o = 16; o > 0; o >>= 1)
            s += __shfl_xor_sync(0xffffffffu, s, o);
        if (lane == 0)
            invN[row] = 1.0f / fmaxf(sqrtf(s), 1e-12f);
    }
    __syncthreads();

    // ---- normalized vectorized store ----
    float4* out4 = reinterpret_cast<float4*>(out);
    for (int i = tid; i < BM * (DDIM / 4); i += THREADS) {
        int r = i >> 6, c = i & 63;
        if (r < rows) {
            float4 v = *reinterpret_cast<const float4*>(&As[r * ASTRIDE + 4 * c]);
            float sc = invN[r];
            v.x *= sc; v.y *= sc; v.z *= sc; v.w *= sc;
            out4[(long)(blockBase + r) * (DDIM / 4) + c] = v;
        }
    }
}

extern "C" void kernel_launch(void* const* d_in, const int* in_sizes, int n_in,
                              void* d_out, int out_size)
{
    const int*   node_idx  = (const int*)  d_in[0];
    const int*   neigh_idx = (const int*)  d_in[1];
    const float* features  = (const float*)d_in[2];
    const float* W         = (const float*)d_in[3];
    const float* b         = (const float*)d_in[4];
    float*       out       = (float*)      d_out;

    const int n_nodes = in_sizes[0];
    const int n_samp  = in_sizes[1] / n_nodes;   // 32

    cudaFuncSetAttribute(gsage_tc_kernel,
                         cudaFuncAttributeMaxDynamicSharedMemorySize, SMEM_BYTES);

    const int grid = (n_nodes + BM - 1) / BM;
    gsage_tc_kernel<<<grid, THREADS, SMEM_BYTES>>>(node_idx, neigh_idx,
                                                   features, W, b, out,
                                                   n_nodes, n_samp);
}